// round 3
// baseline (speedup 1.0000x reference)
#include <cuda_runtime.h>
#include <cuda_fp16.h>

#define NU 200000
#define NI 100000
#define NT 300000          // NU + NI
#define NE 4000000
#define NB ((NT + 1023) / 1024)   // scan blocks = 293

// -------- device scratch (no allocations allowed) --------
__device__ __half2 g_y [NT * 32];  // ping: y = dinv * h, lane owns dims [2l,2l+1]
__device__ __half2 g_yn[NT * 32];  // pong
__device__ int   g_deg[NT];
__device__ int   g_epos[NE];       // within-row slot of each edge (from hist atomic)
__device__ float g_dinv[NT];
__device__ int   g_rowptr[NT + 1];
__device__ int   g_bsum[NB];
__device__ int   g_col[NE];        // dst, CSR-ordered by src

// -------- build: degree histogram, capturing per-edge slot --------
__global__ void k_zero() {
    int i = blockIdx.x * blockDim.x + threadIdx.x;
    if (i < NT) g_deg[i] = 0;
}

__global__ void k_hist(const int4* __restrict__ src4) {
    int i = blockIdx.x * blockDim.x + threadIdx.x;
    if (i < NE / 4) {
        int4 s = src4[i];
        int4 p;
        p.x = atomicAdd(&g_deg[s.x], 1);
        p.y = atomicAdd(&g_deg[s.y], 1);
        p.z = atomicAdd(&g_deg[s.z], 1);
        p.w = atomicAdd(&g_deg[s.w], 1);
        ((int4*)g_epos)[i] = p;
    }
}

// -------- build: 3-phase exclusive scan of deg -> rowptr (dinv fused) --------
__global__ void k_scanA() {
    __shared__ int ws[32];
    int i = blockIdx.x * 1024 + threadIdx.x;
    int v = (i < NT) ? g_deg[i] : 0;
    if (i < NT) g_dinv[i] = rsqrtf((float)v + 1e-8f);
    int lane = threadIdx.x & 31, wid = threadIdx.x >> 5;
    int x = v;
    #pragma unroll
    for (int o = 1; o < 32; o <<= 1) {
        int y = __shfl_up_sync(0xffffffffu, x, o);
        if (lane >= o) x += y;
    }
    if (lane == 31) ws[wid] = x;
    __syncthreads();
    if (wid == 0) {
        int s = ws[lane];
        #pragma unroll
        for (int o = 1; o < 32; o <<= 1) {
            int y = __shfl_up_sync(0xffffffffu, s, o);
            if (lane >= o) s += y;
        }
        ws[lane] = s;
    }
    __syncthreads();
    int excl = x - v + (wid > 0 ? ws[wid - 1] : 0);
    if (i < NT) g_rowptr[i] = excl;
    if (threadIdx.x == 1023) g_bsum[blockIdx.x] = ws[31];
}

__global__ void k_scanB() {
    __shared__ int ws[16];
    int t = threadIdx.x;
    int v = (t < NB) ? g_bsum[t] : 0;
    int lane = t & 31, wid = t >> 5;
    int x = v;
    #pragma unroll
    for (int o = 1; o < 32; o <<= 1) {
        int y = __shfl_up_sync(0xffffffffu, x, o);
        if (lane >= o) x += y;
    }
    if (lane == 31) ws[wid] = x;
    __syncthreads();
    if (wid == 0) {
        int s = (lane < 16) ? ws[lane] : 0;
        #pragma unroll
        for (int o = 1; o < 32; o <<= 1) {
            int y = __shfl_up_sync(0xffffffffu, s, o);
            if (lane >= o) s += y;
        }
        if (lane < 16) ws[lane] = s;
    }
    __syncthreads();
    int excl = x - v + (wid > 0 ? ws[wid - 1] : 0);
    if (t < NB) g_bsum[t] = excl;
    if (t == 0) g_rowptr[NT] = ws[15];   // = NE
}

__global__ void k_scanC() {
    int i = blockIdx.x * blockDim.x + threadIdx.x;
    if (i < NT) g_rowptr[i] += g_bsum[i >> 10];
}

// -------- build: scatter edges into CSR (no atomics) --------
__global__ void k_scatter(const int* __restrict__ src, const int* __restrict__ dst) {
    int e = blockIdx.x * blockDim.x + threadIdx.x;
    if (e < NE) {
        int s = src[e];
        g_col[g_rowptr[s] + g_epos[e]] = dst[e];
    }
}

// -------- init: y0 = dinv * x (fp16); out written by layer 1 --------
__global__ void k_init(const float2* __restrict__ uw, const float2* __restrict__ iw) {
    int i = blockIdx.x * blockDim.x + threadIdx.x;   // half2 element index
    const int NU2 = NU * 32;
    const int NT2 = NT * 32;
    if (i < NT2) {
        float2 v = (i < NU2) ? uw[i] : iw[i - NU2];
        float di = g_dinv[i >> 5];
        g_y[i] = __floats2half2_rn(di * v.x, di * v.y);
    }
}

// -------- SpMM: warp per row; s = sum y[col]; h = dinv*s; y_next = dinv^2*s --------
template<int FIRST, int WRITE_NEXT>
__global__ void __launch_bounds__(256) k_spmm(int parity,
                                              const float2* __restrict__ uw,
                                              const float2* __restrict__ iw,
                                              float2* __restrict__ out) {
    int gw = (blockIdx.x * 256 + threadIdx.x) >> 5;
    if (gw >= NT) return;
    int lane = threadIdx.x & 31;

    const __half2* __restrict__ y  = parity ? g_yn : g_y;
    __half2*       __restrict__ yn = parity ? g_y  : g_yn;

    int beg = g_rowptr[gw], end = g_rowptr[gw + 1];

    float sx0 = 0.f, sy0 = 0.f, sx1 = 0.f, sy1 = 0.f;
    float sx2 = 0.f, sy2 = 0.f, sx3 = 0.f, sy3 = 0.f;
    for (int base = beg; base < end; base += 32) {
        int n = end - base; if (n > 32) n = 32;
        int myc = (base + lane < end) ? g_col[base + lane] : 0;
        int k = 0;
        for (; k + 8 <= n; k += 8) {
            int c0 = __shfl_sync(0xffffffffu, myc, k + 0);
            int c1 = __shfl_sync(0xffffffffu, myc, k + 1);
            int c2 = __shfl_sync(0xffffffffu, myc, k + 2);
            int c3 = __shfl_sync(0xffffffffu, myc, k + 3);
            int c4 = __shfl_sync(0xffffffffu, myc, k + 4);
            int c5 = __shfl_sync(0xffffffffu, myc, k + 5);
            int c6 = __shfl_sync(0xffffffffu, myc, k + 6);
            int c7 = __shfl_sync(0xffffffffu, myc, k + 7);
            float2 v0 = __half22float2(y[c0 * 32 + lane]);
            float2 v1 = __half22float2(y[c1 * 32 + lane]);
            float2 v2 = __half22float2(y[c2 * 32 + lane]);
            float2 v3 = __half22float2(y[c3 * 32 + lane]);
            float2 v4 = __half22float2(y[c4 * 32 + lane]);
            float2 v5 = __half22float2(y[c5 * 32 + lane]);
            float2 v6 = __half22float2(y[c6 * 32 + lane]);
            float2 v7 = __half22float2(y[c7 * 32 + lane]);
            sx0 += v0.x; sy0 += v0.y;
            sx1 += v1.x; sy1 += v1.y;
            sx2 += v2.x; sy2 += v2.y;
            sx3 += v3.x; sy3 += v3.y;
            sx0 += v4.x; sy0 += v4.y;
            sx1 += v5.x; sy1 += v5.y;
            sx2 += v6.x; sy2 += v6.y;
            sx3 += v7.x; sy3 += v7.y;
        }
        if (k + 4 <= n) {
            int c0 = __shfl_sync(0xffffffffu, myc, k + 0);
            int c1 = __shfl_sync(0xffffffffu, myc, k + 1);
            int c2 = __shfl_sync(0xffffffffu, myc, k + 2);
            int c3 = __shfl_sync(0xffffffffu, myc, k + 3);
            float2 v0 = __half22float2(y[c0 * 32 + lane]);
            float2 v1 = __half22float2(y[c1 * 32 + lane]);
            float2 v2 = __half22float2(y[c2 * 32 + lane]);
            float2 v3 = __half22float2(y[c3 * 32 + lane]);
            sx0 += v0.x; sy0 += v0.y;
            sx1 += v1.x; sy1 += v1.y;
            sx2 += v2.x; sy2 += v2.y;
            sx3 += v3.x; sy3 += v3.y;
            k += 4;
        }
        for (; k < n; k++) {
            int c = __shfl_sync(0xffffffffu, myc, k);
            float2 v = __half22float2(y[c * 32 + lane]);
            sx0 += v.x; sy0 += v.y;
        }
    }
    float s_x = (sx0 + sx1) + (sx2 + sx3);
    float s_y = (sy0 + sy1) + (sy2 + sy3);

    float di = g_dinv[gw];
    float hx = di * s_x, hy = di * s_y;       // this layer's h contribution
    int o = gw * 32 + lane;
    if (WRITE_NEXT)
        yn[o] = __floats2half2_rn(di * hx, di * hy);   // dinv^2 * s
    if (FIRST) {
        float2 v = (gw < NU) ? uw[o] : iw[o - NU * 32];
        out[o] = make_float2(0.25f * (v.x + hx), 0.25f * (v.y + hy));
    } else {
        float2 a = out[o];
        a.x += 0.25f * hx; a.y += 0.25f * hy;
        out[o] = a;
    }
}

extern "C" void kernel_launch(void* const* d_in, const int* in_sizes, int n_in,
                              void* d_out, int out_size) {
    const float* uw  = (const float*)d_in[0];
    const float* iw  = (const float*)d_in[1];
    const int*   src = (const int*)d_in[2];
    const int*   dst = (const int*)d_in[3];
    float* out = (float*)d_out;

    // CSR build
    k_zero<<<(NT + 255) / 256, 256>>>();
    k_hist<<<(NE / 4 + 255) / 256, 256>>>((const int4*)src);
    k_scanA<<<NB, 1024>>>();
    k_scanB<<<1, 512>>>();
    k_scanC<<<(NT + 1023) / 1024, 1024>>>();
    k_scatter<<<(NE + 255) / 256, 256>>>(src, dst);

    // init y0 = dinv*x (fp16)
    k_init<<<(NT * 32 + 255) / 256, 256>>>((const float2*)uw, (const float2*)iw);

    // 3 propagation layers, ping-pong y between g_y and g_yn
    int nblk = (NT * 32 + 255) / 256;
    k_spmm<1, 1><<<nblk, 256>>>(0, (const float2*)uw, (const float2*)iw, (float2*)out);
    k_spmm<0, 1><<<nblk, 256>>>(1, (const float2*)uw, (const float2*)iw, (float2*)out);
    k_spmm<0, 0><<<nblk, 256>>>(0, (const float2*)uw, (const float2*)iw, (float2*)out);
}

// round 4
// speedup vs baseline: 1.1702x; 1.1702x over previous
#include <cuda_runtime.h>
#include <cuda_fp16.h>

#define NU 200000
#define NI 100000
#define NT 300000          // NU + NI
#define NE 4000000
#define NB ((NT + 1023) / 1024)   // scan blocks = 293

// -------- device scratch (no allocations allowed) --------
__device__ __half2 g_a[NT * 32];   // y0 -> (L3) h3
__device__ __half2 g_b[NT * 32];   // y1
__device__ __half2 g_c[NT * 32];   // y2
__device__ int   g_deg[NT];
__device__ int   g_pos[NT];
__device__ float g_dinv[NT];
__device__ int   g_rowptr[NT + 1];
__device__ int   g_bsum[NB];
__device__ int   g_col[NE];        // dst, CSR-ordered by src

__device__ __forceinline__ __half2* buf(int s) {
    return (s == 0) ? g_a : (s == 1) ? g_b : g_c;
}

// -------- build: degree histogram --------
__global__ void k_zero() {
    int i = blockIdx.x * blockDim.x + threadIdx.x;
    if (i < NT) { g_deg[i] = 0; g_pos[i] = 0; }
}

__global__ void k_hist(const int4* __restrict__ src4) {
    int i = blockIdx.x * blockDim.x + threadIdx.x;
    if (i < NE / 4) {
        int4 s = src4[i];
        atomicAdd(&g_deg[s.x], 1);
        atomicAdd(&g_deg[s.y], 1);
        atomicAdd(&g_deg[s.z], 1);
        atomicAdd(&g_deg[s.w], 1);
    }
}

// -------- build: 3-phase exclusive scan of deg -> rowptr (dinv fused) --------
__global__ void k_scanA() {
    __shared__ int ws[32];
    int i = blockIdx.x * 1024 + threadIdx.x;
    int v = (i < NT) ? g_deg[i] : 0;
    if (i < NT) g_dinv[i] = rsqrtf((float)v + 1e-8f);
    int lane = threadIdx.x & 31, wid = threadIdx.x >> 5;
    int x = v;
    #pragma unroll
    for (int o = 1; o < 32; o <<= 1) {
        int y = __shfl_up_sync(0xffffffffu, x, o);
        if (lane >= o) x += y;
    }
    if (lane == 31) ws[wid] = x;
    __syncthreads();
    if (wid == 0) {
        int s = ws[lane];
        #pragma unroll
        for (int o = 1; o < 32; o <<= 1) {
            int y = __shfl_up_sync(0xffffffffu, s, o);
            if (lane >= o) s += y;
        }
        ws[lane] = s;
    }
    __syncthreads();
    int excl = x - v + (wid > 0 ? ws[wid - 1] : 0);
    if (i < NT) g_rowptr[i] = excl;
    if (threadIdx.x == 1023) g_bsum[blockIdx.x] = ws[31];
}

__global__ void k_scanB() {
    __shared__ int ws[16];
    int t = threadIdx.x;
    int v = (t < NB) ? g_bsum[t] : 0;
    int lane = t & 31, wid = t >> 5;
    int x = v;
    #pragma unroll
    for (int o = 1; o < 32; o <<= 1) {
        int y = __shfl_up_sync(0xffffffffu, x, o);
        if (lane >= o) x += y;
    }
    if (lane == 31) ws[wid] = x;
    __syncthreads();
    if (wid == 0) {
        int s = (lane < 16) ? ws[lane] : 0;
        #pragma unroll
        for (int o = 1; o < 32; o <<= 1) {
            int y = __shfl_up_sync(0xffffffffu, s, o);
            if (lane >= o) s += y;
        }
        if (lane < 16) ws[lane] = s;
    }
    __syncthreads();
    int excl = x - v + (wid > 0 ? ws[wid - 1] : 0);
    if (t < NB) g_bsum[t] = excl;
    if (t == 0) g_rowptr[NT] = ws[15];   // = NE
}

__global__ void k_scanC() {
    int i = blockIdx.x * blockDim.x + threadIdx.x;
    if (i < NT) g_rowptr[i] += g_bsum[i >> 10];
}

// -------- build: scatter edges into CSR (atomic cursor; spread addrs = cheap) --------
__global__ void k_scatter(const int* __restrict__ src, const int* __restrict__ dst) {
    int e = blockIdx.x * blockDim.x + threadIdx.x;
    if (e < NE) {
        int s = src[e];
        int p = atomicAdd(&g_pos[s], 1);
        g_col[g_rowptr[s] + p] = dst[e];
    }
}

// -------- init: y0 = dinv * x (fp16) into buffer A --------
__global__ void k_init(const float2* __restrict__ uw, const float2* __restrict__ iw) {
    int i = blockIdx.x * blockDim.x + threadIdx.x;   // half2 element index
    const int NU2 = NU * 32;
    const int NT2 = NT * 32;
    if (i < NT2) {
        float2 v = (i < NU2) ? uw[i] : iw[i - NU2];
        float di = g_dinv[i >> 5];
        g_a[i] = __floats2half2_rn(di * v.x, di * v.y);
    }
}

// -------- SpMM: warp per row; s = sum y[col]; store dinv^2*s (y) or dinv*s (h) --------
// MODE 0: dst = dinv^2 * s (propagated y for next layer)
// MODE 1: dst = dinv * s   (h itself, last layer)
template<int S, int DBUF, int MODE>
__global__ void __launch_bounds__(256) k_spmm() {
    int gw = (blockIdx.x * 256 + threadIdx.x) >> 5;
    if (gw >= NT) return;
    int lane = threadIdx.x & 31;

    const __half2* __restrict__ y = buf(S);
    __half2*       __restrict__ w = buf(DBUF);

    int beg = g_rowptr[gw], end = g_rowptr[gw + 1];

    float sx0 = 0.f, sy0 = 0.f, sx1 = 0.f, sy1 = 0.f;
    for (int base = beg; base < end; base += 32) {
        int n = end - base; if (n > 32) n = 32;
        int myc = (base + lane < end) ? g_col[base + lane] : 0;
        int k = 0;
        for (; k + 4 <= n; k += 4) {
            int c0 = __shfl_sync(0xffffffffu, myc, k + 0);
            int c1 = __shfl_sync(0xffffffffu, myc, k + 1);
            int c2 = __shfl_sync(0xffffffffu, myc, k + 2);
            int c3 = __shfl_sync(0xffffffffu, myc, k + 3);
            float2 v0 = __half22float2(y[c0 * 32 + lane]);
            float2 v1 = __half22float2(y[c1 * 32 + lane]);
            float2 v2 = __half22float2(y[c2 * 32 + lane]);
            float2 v3 = __half22float2(y[c3 * 32 + lane]);
            sx0 += v0.x; sy0 += v0.y;
            sx1 += v1.x; sy1 += v1.y;
            sx0 += v2.x; sy0 += v2.y;
            sx1 += v3.x; sy1 += v3.y;
        }
        for (; k < n; k++) {
            int c = __shfl_sync(0xffffffffu, myc, k);
            float2 v = __half22float2(y[c * 32 + lane]);
            sx0 += v.x; sy0 += v.y;
        }
    }
    float s_x = sx0 + sx1, s_y = sy0 + sy1;

    float di = g_dinv[gw];
    float f = (MODE == 0) ? di * di : di;
    w[gw * 32 + lane] = __floats2half2_rn(f * s_x, f * s_y);
}

// -------- final: out = 0.25 * (x + y1/dinv + y2/dinv + h3) --------
__global__ void k_final(const float2* __restrict__ uw, const float2* __restrict__ iw,
                        float2* __restrict__ out) {
    int i = blockIdx.x * blockDim.x + threadIdx.x;   // half2 element index
    const int NU2 = NU * 32;
    const int NT2 = NT * 32;
    if (i >= NT2) return;
    float2 v = (i < NU2) ? uw[i] : iw[i - NU2];
    float di = g_dinv[i >> 5];
    float inv = __frcp_rn(di);                        // = sqrt(deg + 1e-8)
    float2 y1 = __half22float2(g_b[i]);
    float2 y2 = __half22float2(g_c[i]);
    float2 h3 = __half22float2(g_a[i]);
    float ox = 0.25f * (v.x + inv * (y1.x + y2.x) + h3.x);
    float oy = 0.25f * (v.y + inv * (y1.y + y2.y) + h3.y);
    out[i] = make_float2(ox, oy);
}

extern "C" void kernel_launch(void* const* d_in, const int* in_sizes, int n_in,
                              void* d_out, int out_size) {
    const float* uw  = (const float*)d_in[0];
    const float* iw  = (const float*)d_in[1];
    const int*   src = (const int*)d_in[2];
    const int*   dst = (const int*)d_in[3];
    float* out = (float*)d_out;

    // CSR build
    k_zero<<<(NT + 255) / 256, 256>>>();
    k_hist<<<(NE / 4 + 255) / 256, 256>>>((const int4*)src);
    k_scanA<<<NB, 1024>>>();
    k_scanB<<<1, 512>>>();
    k_scanC<<<(NT + 1023) / 1024, 1024>>>();
    k_scatter<<<(NE + 255) / 256, 256>>>(src, dst);

    // init y0 = dinv*x (fp16) into A
    k_init<<<(NT * 32 + 255) / 256, 256>>>((const float2*)uw, (const float2*)iw);

    // 3 pure-propagation layers: A->B (y1), B->C (y2), C->A (h3)
    int nblk = (NT * 32 + 255) / 256;
    k_spmm<0, 1, 0><<<nblk, 256>>>();
    k_spmm<1, 2, 0><<<nblk, 256>>>();
    k_spmm<2, 0, 1><<<nblk, 256>>>();

    // fused epilogue
    k_final<<<(NT * 32 + 255) / 256, 256>>>((const float2*)uw, (const float2*)iw,
                                            (float2*)out);
}

// round 5
// speedup vs baseline: 1.2385x; 1.0584x over previous
#include <cuda_runtime.h>
#include <cuda_fp16.h>

#define NU 200000
#define NI 100000
#define NT 300000          // NU + NI
#define NE 4000000
#define NB ((NT + 1023) / 1024)   // scan blocks = 293

// -------- device scratch (no allocations allowed) --------
__device__ __half2 g_a[NT * 32];   // y0
__device__ __half2 g_b[NT * 32];   // y1
__device__ __half2 g_c[NT * 32];   // y2
__device__ int   g_deg[NT];
__device__ int   g_pos[NT];
__device__ float g_dinv[NT];
__device__ int   g_rowptr[NT + 1];
__device__ int   g_bsum[NB];
__device__ int   g_col[NE];        // dst, CSR-ordered by src

__device__ __forceinline__ __half2* buf(int s) {
    return (s == 0) ? g_a : (s == 1) ? g_b : g_c;
}

// -------- build: degree histogram --------
__global__ void k_hist(const int4* __restrict__ src4) {
    int i = blockIdx.x * blockDim.x + threadIdx.x;
    if (i < NE / 4) {
        int4 s = src4[i];
        atomicAdd(&g_deg[s.x], 1);
        atomicAdd(&g_deg[s.y], 1);
        atomicAdd(&g_deg[s.z], 1);
        atomicAdd(&g_deg[s.w], 1);
    }
}

// -------- build: scan phase A (dinv fused) --------
__global__ void k_scanA() {
    __shared__ int ws[32];
    int i = blockIdx.x * 1024 + threadIdx.x;
    int v = (i < NT) ? g_deg[i] : 0;
    if (i < NT) g_dinv[i] = rsqrtf((float)v + 1e-8f);
    int lane = threadIdx.x & 31, wid = threadIdx.x >> 5;
    int x = v;
    #pragma unroll
    for (int o = 1; o < 32; o <<= 1) {
        int y = __shfl_up_sync(0xffffffffu, x, o);
        if (lane >= o) x += y;
    }
    if (lane == 31) ws[wid] = x;
    __syncthreads();
    if (wid == 0) {
        int s = ws[lane];
        #pragma unroll
        for (int o = 1; o < 32; o <<= 1) {
            int y = __shfl_up_sync(0xffffffffu, s, o);
            if (lane >= o) s += y;
        }
        ws[lane] = s;
    }
    __syncthreads();
    int excl = x - v + (wid > 0 ? ws[wid - 1] : 0);
    if (i < NT) g_rowptr[i] = excl;
    if (threadIdx.x == 1023) g_bsum[blockIdx.x] = ws[31];
}

// -------- build: scan phase B (single block over block sums) --------
__global__ void k_scanB() {
    __shared__ int ws[16];
    int t = threadIdx.x;
    int v = (t < NB) ? g_bsum[t] : 0;
    int lane = t & 31, wid = t >> 5;
    int x = v;
    #pragma unroll
    for (int o = 1; o < 32; o <<= 1) {
        int y = __shfl_up_sync(0xffffffffu, x, o);
        if (lane >= o) x += y;
    }
    if (lane == 31) ws[wid] = x;
    __syncthreads();
    if (wid == 0) {
        int s = (lane < 16) ? ws[lane] : 0;
        #pragma unroll
        for (int o = 1; o < 32; o <<= 1) {
            int y = __shfl_up_sync(0xffffffffu, s, o);
            if (lane >= o) s += y;
        }
        if (lane < 16) ws[lane] = s;
    }
    __syncthreads();
    int excl = x - v + (wid > 0 ? ws[wid - 1] : 0);
    if (t < NB) g_bsum[t] = excl;
    if (t == 0) g_rowptr[NT] = ws[15];   // = NE
}

// -------- fused: scanC (rowptr fix-up) + init (y0 = dinv*x fp16) --------
__global__ void k_fixinit(const float2* __restrict__ uw, const float2* __restrict__ iw) {
    int i = blockIdx.x * blockDim.x + threadIdx.x;   // half2 element index
    const int NU2 = NU * 32;
    const int NT2 = NT * 32;
    if (i < NT) g_rowptr[i] += g_bsum[i >> 10];
    if (i < NT2) {
        float2 v = (i < NU2) ? uw[i] : iw[i - NU2];
        float di = g_dinv[i >> 5];
        g_a[i] = __floats2half2_rn(di * v.x, di * v.y);
    }
}

// -------- build: scatter edges into CSR (atomic cursor; spread addrs = cheap) --------
__global__ void k_scatter(const int* __restrict__ src, const int* __restrict__ dst) {
    int e = blockIdx.x * blockDim.x + threadIdx.x;
    if (e < NE) {
        int s = src[e];
        int p = atomicAdd(&g_pos[s], 1);
        g_col[g_rowptr[s] + p] = dst[e];
    }
}

// -------- SpMM: warp per row; s = sum y[col] --------
// LAST=0: store dinv^2*s (propagated y). LAST=1: fused epilogue writes out.
template<int S, int DBUF, int LAST>
__global__ void __launch_bounds__(256) k_spmm(const float2* __restrict__ uw,
                                              const float2* __restrict__ iw,
                                              float2* __restrict__ out) {
    int gw = (blockIdx.x * 256 + threadIdx.x) >> 5;
    if (gw >= NT) return;
    int lane = threadIdx.x & 31;

    const __half2* __restrict__ y = buf(S);

    int beg = g_rowptr[gw], end = g_rowptr[gw + 1];

    float sx0 = 0.f, sy0 = 0.f, sx1 = 0.f, sy1 = 0.f;
    for (int base = beg; base < end; base += 32) {
        int n = end - base; if (n > 32) n = 32;
        int myc = (base + lane < end) ? g_col[base + lane] : 0;
        int k = 0;
        for (; k + 4 <= n; k += 4) {
            int c0 = __shfl_sync(0xffffffffu, myc, k + 0);
            int c1 = __shfl_sync(0xffffffffu, myc, k + 1);
            int c2 = __shfl_sync(0xffffffffu, myc, k + 2);
            int c3 = __shfl_sync(0xffffffffu, myc, k + 3);
            float2 v0 = __half22float2(y[c0 * 32 + lane]);
            float2 v1 = __half22float2(y[c1 * 32 + lane]);
            float2 v2 = __half22float2(y[c2 * 32 + lane]);
            float2 v3 = __half22float2(y[c3 * 32 + lane]);
            sx0 += v0.x; sy0 += v0.y;
            sx1 += v1.x; sy1 += v1.y;
            sx0 += v2.x; sy0 += v2.y;
            sx1 += v3.x; sy1 += v3.y;
        }
        for (; k < n; k++) {
            int c = __shfl_sync(0xffffffffu, myc, k);
            float2 v = __half22float2(y[c * 32 + lane]);
            sx0 += v.x; sy0 += v.y;
        }
    }
    float s_x = sx0 + sx1, s_y = sy0 + sy1;

    float di = g_dinv[gw];
    int o = gw * 32 + lane;
    if (!LAST) {
        __half2* __restrict__ w = buf(DBUF);
        float f = di * di;
        w[o] = __floats2half2_rn(f * s_x, f * s_y);
    } else {
        // h3 = di*s; out = 0.25*(x + inv*(y1+y2) + h3)
        float hx = di * s_x, hy = di * s_y;
        float inv = __frcp_rn(di);                 // = sqrt(deg + 1e-8)
        float2 v  = (gw < NU) ? uw[o] : iw[o - NU * 32];
        float2 y1 = __half22float2(g_b[o]);
        float2 y2 = __half22float2(g_c[o]);
        out[o] = make_float2(0.25f * (v.x + inv * (y1.x + y2.x) + hx),
                             0.25f * (v.y + inv * (y1.y + y2.y) + hy));
    }
}

extern "C" void kernel_launch(void* const* d_in, const int* in_sizes, int n_in,
                              void* d_out, int out_size) {
    const float* uw  = (const float*)d_in[0];
    const float* iw  = (const float*)d_in[1];
    const int*   src = (const int*)d_in[2];
    const int*   dst = (const int*)d_in[3];
    float* out = (float*)d_out;

    // zero deg + pos via memset nodes (not kernel launches)
    void *p_deg = nullptr, *p_pos = nullptr;
    cudaGetSymbolAddress(&p_deg, g_deg);
    cudaGetSymbolAddress(&p_pos, g_pos);
    cudaMemsetAsync(p_deg, 0, NT * sizeof(int));
    cudaMemsetAsync(p_pos, 0, NT * sizeof(int));

    // CSR build + init  (kernel launches: 1..5)
    k_hist<<<(NE / 4 + 255) / 256, 256>>>((const int4*)src);
    k_scanA<<<NB, 1024>>>();
    k_scanB<<<1, 512>>>();
    k_fixinit<<<(NT * 32 + 255) / 256, 256>>>((const float2*)uw, (const float2*)iw);
    k_scatter<<<(NE + 255) / 256, 256>>>(src, dst);

    // 3 propagation layers (launches 6..8); layer 3 fuses the epilogue
    int nblk = (NT * 32 + 255) / 256;
    k_spmm<0, 1, 0><<<nblk, 256>>>((const float2*)uw, (const float2*)iw, (float2*)out);
    k_spmm<1, 2, 0><<<nblk, 256>>>((const float2*)uw, (const float2*)iw, (float2*)out);
    k_spmm<2, 0, 1><<<nblk, 256>>>((const float2*)uw, (const float2*)iw, (float2*)out);
}